// round 5
// baseline (speedup 1.0000x reference)
#include <cuda_runtime.h>
#include <cuda_fp16.h>

// Factorized ray-marching: x@W1+b1 = p1 + alpha*u.
// R5: GEMM via HMMA mma.sync.m16n8k16 (f16 in, f32 accum). W1 pre-packed into
// per-lane B fragments (coalesced uint2). One warp = 16 rows. Iteration phase
// unchanged (f16x2 tanh, 8-lane groups, 3-shfl reduction).

#define D_DIM 128
#define H_DIM 256
#define KT    8            // k-tiles of 16 over D=128
#define NT    32           // n-tiles of 8 over H=256
#define WROWS 16           // rows per warp
#define WARPS 4            // warps per block
#define BROWS (WROWS * WARPS)  // 64 rows per block
#define UPAD  (H_DIM + 8)      // padded u row (conflict-free)

__device__ float   g_p1[H_DIM];
__device__ __half2 g_p1h2[H_DIM / 2];
__device__ __half2 g_w2h2[H_DIM / 2];
__device__ uint2   g_Bfrag[KT * NT * 32];   // 64 KB: W1 in mma B-fragment layout

static __device__ __forceinline__ float tanh_fast(float x) {
    float y; asm("tanh.approx.f32 %0, %1;" : "=f"(y) : "f"(x)); return y;
}
static __device__ __forceinline__ __half2 tanh2_fast(__half2 x) {
    __half2 y;
    asm("tanh.approx.f16x2 %0, %1;" : "=r"(*(unsigned*)&y) : "r"(*(unsigned*)&x));
    return y;
}
static __device__ __forceinline__ unsigned h2bits(__half2 v) { return *(unsigned*)&v; }
static __device__ __forceinline__ unsigned hmul2b(unsigned a, __half2 s) {
    __half2 va = *(__half2*)&a;
    __half2 r = __hmul2(va, s);
    return *(unsigned*)&r;
}
static __device__ __forceinline__ void mma16816(float& c0, float& c1, float& c2, float& c3,
                                                unsigned a0, unsigned a1, unsigned a2, unsigned a3,
                                                unsigned b0, unsigned b1) {
    asm volatile("mma.sync.aligned.m16n8k16.row.col.f32.f16.f16.f32 "
                 "{%0,%1,%2,%3}, {%4,%5,%6,%7}, {%8,%9}, {%0,%1,%2,%3};"
                 : "+f"(c0), "+f"(c1), "+f"(c2), "+f"(c3)
                 : "r"(a0), "r"(a1), "r"(a2), "r"(a3), "r"(b0), "r"(b1));
}

// prep: block 0 computes p1 (f32) + half copies; blocks 1..32 pack W1 B-fragments.
__global__ void prep_kernel(const float* __restrict__ pivot,
                            const float* __restrict__ W1,
                            const float* __restrict__ b1,
                            const float* __restrict__ w2) {
    __shared__ float sp1[H_DIM];
    const int j = threadIdx.x;
    if (blockIdx.x == 0) {
        float s = b1[j];
#pragma unroll 8
        for (int d = 0; d < D_DIM; ++d)
            s = fmaf(pivot[d], W1[d * H_DIM + j], s);
        g_p1[j] = s;
        sp1[j] = s;
        __syncthreads();
        if (j < H_DIM / 2) {
            g_p1h2[j] = __floats2half2_rn(sp1[2 * j], sp1[2 * j + 1]);
            g_w2h2[j] = __floats2half2_rn(w2[2 * j], w2[2 * j + 1]);
        }
    } else {
        // entry e in [0, KT*NT*32): tile = e>>5, lane = e&31
        const int e = (blockIdx.x - 1) * 256 + j;       // 32 blocks * 256 = 8192
        const int tile = e >> 5;
        const int lane = e & 31;
        const int kt = tile / NT;
        const int nt = tile % NT;
        const int g = lane >> 2, t4 = lane & 3;
        const int k0 = kt * 16 + t4 * 2;
        const int col = nt * 8 + g;
        __half2 b0 = __floats2half2_rn(W1[(size_t)k0 * H_DIM + col],
                                       W1[(size_t)(k0 + 1) * H_DIM + col]);
        __half2 b1v = __floats2half2_rn(W1[(size_t)(k0 + 8) * H_DIM + col],
                                        W1[(size_t)(k0 + 9) * H_DIM + col]);
        g_Bfrag[tile * 32 + lane] = make_uint2(h2bits(b0), h2bits(b1v));
    }
}

__global__ __launch_bounds__(128)
void raymarch_kernel(const float* __restrict__ r,
                     const float* __restrict__ s_in,
                     const float* __restrict__ pivot,
                     const float* __restrict__ b2,
                     const int* __restrict__ n_iter_ptr,
                     float* __restrict__ out,
                     int B) {
    __shared__ __half u_sh[BROWS][UPAD];     // 64 x 264 halves = 33 KB
    __shared__ float  inv_sh[BROWS];

    const int lane = threadIdx.x & 31;
    const int wib  = threadIdx.x >> 5;
    const int warp = blockIdx.x * WARPS + wib;
    const int row0 = warp * WROWS;           // absolute first row of this warp
    const int lrow0 = wib * WROWS;           // block-local first row
    if (row0 >= B) return;

    // ===== A fragments straight from gmem (quad covers full row => norm too) =====
    const int g4 = lane >> 2, t4 = lane & 3;
    const int rA = row0 + g4;                // low row of this lane's fragments
    const int rB = rA + 8;
    const float* pA = r + (size_t)rA * D_DIM;
    const float* pB = r + (size_t)rB * D_DIM;

    unsigned a0[KT], a1[KT], a2[KT], a3[KT];
    float sl = 0.f, sh = 0.f;
#pragma unroll
    for (int kt = 0; kt < KT; ++kt) {
        const int base = kt * 16 + t4 * 2;
        float2 v0 = *(const float2*)(pA + base);
        float2 v1 = *(const float2*)(pB + base);
        float2 v2 = *(const float2*)(pA + base + 8);
        float2 v3 = *(const float2*)(pB + base + 8);
        sl = fmaf(v0.x, v0.x, fmaf(v0.y, v0.y, fmaf(v2.x, v2.x, fmaf(v2.y, v2.y, sl))));
        sh = fmaf(v1.x, v1.x, fmaf(v1.y, v1.y, fmaf(v3.x, v3.x, fmaf(v3.y, v3.y, sh))));
        a0[kt] = h2bits(__floats2half2_rn(v0.x, v0.y));
        a1[kt] = h2bits(__floats2half2_rn(v1.x, v1.y));
        a2[kt] = h2bits(__floats2half2_rn(v2.x, v2.y));
        a3[kt] = h2bits(__floats2half2_rn(v3.x, v3.y));
    }
    // quad-reduce sums of squares (offsets 1,2 stay within the quad)
    sl += __shfl_xor_sync(0xffffffffu, sl, 1);
    sl += __shfl_xor_sync(0xffffffffu, sl, 2);
    sh += __shfl_xor_sync(0xffffffffu, sh, 1);
    sh += __shfl_xor_sync(0xffffffffu, sh, 2);
    const float invl = rsqrtf(sl);
    const float invh = rsqrtf(sh);
    const __half2 il2 = __float2half2_rn(invl);
    const __half2 ih2 = __float2half2_rn(invh);
#pragma unroll
    for (int kt = 0; kt < KT; ++kt) {
        a0[kt] = hmul2b(a0[kt], il2);
        a2[kt] = hmul2b(a2[kt], il2);
        a1[kt] = hmul2b(a1[kt], ih2);
        a3[kt] = hmul2b(a3[kt], ih2);
    }
    if (t4 == 0) {
        inv_sh[lrow0 + g4]     = invl;
        inv_sh[lrow0 + g4 + 8] = invh;
    }

    // ===== HMMA GEMM: 4 chunks of 64 cols (8 n-tiles, 32 f32 accums) =====
#pragma unroll
    for (int c = 0; c < 4; ++c) {
        float acc[8][4];
#pragma unroll
        for (int t = 0; t < 8; ++t)
#pragma unroll
            for (int q = 0; q < 4; ++q) acc[t][q] = 0.f;

#pragma unroll
        for (int kt = 0; kt < KT; ++kt) {
#pragma unroll
            for (int t = 0; t < 8; ++t) {
                const int tile = kt * NT + c * 8 + t;
                uint2 bf = g_Bfrag[tile * 32 + lane];
                mma16816(acc[t][0], acc[t][1], acc[t][2], acc[t][3],
                         a0[kt], a1[kt], a2[kt], a3[kt], bf.x, bf.y);
            }
        }
        // store u chunk: lane covers rows {g4, g4+8}, cols (c*8+t)*8 + t4*2
#pragma unroll
        for (int t = 0; t < 8; ++t) {
            const int col = (c * 8 + t) * 8 + t4 * 2;
            *(__half2*)&u_sh[lrow0 + g4][col]     = __floats2half2_rn(acc[t][0], acc[t][1]);
            *(__half2*)&u_sh[lrow0 + g4 + 8][col] = __floats2half2_rn(acc[t][2], acc[t][3]);
        }
    }
    __syncwarp();

    // ===== Iteration phase: 8-lane group per row, 4 quads of 4 rows =====
    const int gB = lane >> 3, lB = lane & 7;
    const float b2v = b2[0];
    const int n = n_iter_ptr ? *n_iter_ptr : 20;

    __half2 p12[16], w22[16];
#pragma unroll
    for (int q = 0; q < 16; ++q) { p12[q] = g_p1h2[lB * 16 + q]; w22[q] = g_w2h2[lB * 16 + q]; }
    const __half2 h2z = __floats2half2_rn(0.f, 0.f);

#pragma unroll
    for (int quad = 0; quad < 4; ++quad) {
        const int lrow = lrow0 + quad * 4 + gB;
        const int grow = blockIdx.x * BROWS + lrow;

        __half2 u2[16];
        {
            const uint4* up = (const uint4*)(&u_sh[lrow][lB * 32]);
#pragma unroll
            for (int v = 0; v < 4; ++v) {
                uint4 w = up[v];
                u2[v * 4 + 0] = *(__half2*)&w.x;
                u2[v * 4 + 1] = *(__half2*)&w.y;
                u2[v * 4 + 2] = *(__half2*)&w.z;
                u2[v * 4 + 3] = *(__half2*)&w.w;
            }
        }

        float alpha = 0.f;
        for (int it = 0; it < n; ++it) {
            const __half2 a2h = __float2half2_rn(alpha);
            __half2 acc2a = h2z, acc2b = h2z;
#pragma unroll
            for (int q = 0; q < 16; q += 2) {
                __half2 za = __hfma2(a2h, u2[q],     p12[q]);
                __half2 zb = __hfma2(a2h, u2[q + 1], p12[q + 1]);
                acc2a = __hfma2(tanh2_fast(za), w22[q],     acc2a);
                acc2b = __hfma2(tanh2_fast(zb), w22[q + 1], acc2b);
            }
            __half2 acc2 = __hadd2(acc2a, acc2b);
            float accf = __low2float(acc2) + __high2float(acc2);
            accf += __shfl_xor_sync(0xffffffffu, accf, 1);
            accf += __shfl_xor_sync(0xffffffffu, accf, 2);
            accf += __shfl_xor_sync(0xffffffffu, accf, 4);
            alpha += 0.05f * (1.0f + tanh_fast(accf + b2v));
        }

        // output row: lane owns dims 16*lB .. 16*lB+15
        if (grow < B) {
            const float sv = s_in[grow];
            const float sig = 1.0f / (1.0f + __expf(-sv));
            const float fscale = sig * alpha * inv_sh[lrow];

            const float4* rv4 = (const float4*)(r + (size_t)grow * D_DIM) + lB * 4;
            const float4* pv4 = (const float4*)pivot + lB * 4;
            float4* ov4 = (float4*)(out + (size_t)grow * D_DIM) + lB * 4;
#pragma unroll
            for (int jj = 0; jj < 4; ++jj) {
                float4 rv = rv4[jj];
                float4 pv = pv4[jj];
                float4 o;
                o.x = fmaf(fscale, rv.x, pv.x);
                o.y = fmaf(fscale, rv.y, pv.y);
                o.z = fmaf(fscale, rv.z, pv.z);
                o.w = fmaf(fscale, rv.w, pv.w);
                ov4[jj] = o;
            }
        }
    }
}

extern "C" void kernel_launch(void* const* d_in, const int* in_sizes, int n_in,
                              void* d_out, int out_size) {
    const float* r     = (const float*)d_in[0];   // [B,128]
    const float* s     = (const float*)d_in[1];   // [B,1]
    const float* pivot = (const float*)d_in[2];   // [128]
    const float* W1    = (const float*)d_in[3];   // [128,256]
    const float* b1    = (const float*)d_in[4];   // [256]
    const float* w2    = (const float*)d_in[5];   // [256]
    const float* b2    = (const float*)d_in[6];   // [1]
    const int* n_iter  = (n_in > 7) ? (const int*)d_in[7] : nullptr;
    float* out = (float*)d_out;

    const int B = in_sizes[0] / D_DIM;

    prep_kernel<<<33, 256>>>(pivot, W1, b1, w2);   // block 0: p1; blocks 1..32: B-frags

    const int blocks = (B + BROWS - 1) / BROWS;    // 64 rows per block
    raymarch_kernel<<<blocks, 128>>>(r, s, pivot, b2, n_iter, out, B);
}

// round 6
// speedup vs baseline: 1.0238x; 1.0238x over previous
#include <cuda_runtime.h>
#include <cuda_fp16.h>

// Factorized ray-marching: x@W1+b1 = p1 + alpha*u.
// R6: two-kernel split. Kernel 1: HMMA GEMM (warp=16 rows) -> u staged to a
// 16MB __device__ buffer via coalesced smem copy-out. Kernel 2: 20-step f16x2
// recurrence with 4 rows/warp (8-lane groups) at full occupancy.

#define D_DIM 128
#define H_DIM 256
#define KT    8            // k-tiles of 16 over D=128
#define NT    32           // n-tiles of 8 over H=256
#define WROWS 16           // rows per warp (GEMM)
#define WARPS 4            // warps per block (GEMM)
#define BROWS (WROWS * WARPS)
#define UPAD  (H_DIM + 8)
#define B_MAX 32768

__device__ float   g_p1[H_DIM];
__device__ __half2 g_p1h2[H_DIM / 2];
__device__ __half2 g_w2h2[H_DIM / 2];
__device__ uint2   g_Bfrag[KT * NT * 32];       // 64 KB: W1 B-fragments
__device__ __half  g_u[(size_t)B_MAX * H_DIM];  // 16 MB: normalized u rows

static __device__ __forceinline__ float tanh_fast(float x) {
    float y; asm("tanh.approx.f32 %0, %1;" : "=f"(y) : "f"(x)); return y;
}
static __device__ __forceinline__ __half2 tanh2_fast(__half2 x) {
    __half2 y;
    asm("tanh.approx.f16x2 %0, %1;" : "=r"(*(unsigned*)&y) : "r"(*(unsigned*)&x));
    return y;
}
static __device__ __forceinline__ unsigned h2bits(__half2 v) { return *(unsigned*)&v; }
static __device__ __forceinline__ unsigned hmul2b(unsigned a, __half2 s) {
    __half2 va = *(__half2*)&a;
    __half2 r = __hmul2(va, s);
    return *(unsigned*)&r;
}
static __device__ __forceinline__ void mma16816(float& c0, float& c1, float& c2, float& c3,
                                                unsigned a0, unsigned a1, unsigned a2, unsigned a3,
                                                unsigned b0, unsigned b1) {
    asm volatile("mma.sync.aligned.m16n8k16.row.col.f32.f16.f16.f32 "
                 "{%0,%1,%2,%3}, {%4,%5,%6,%7}, {%8,%9}, {%0,%1,%2,%3};"
                 : "+f"(c0), "+f"(c1), "+f"(c2), "+f"(c3)
                 : "r"(a0), "r"(a1), "r"(a2), "r"(a3), "r"(b0), "r"(b1));
}

// prep: block 0 computes p1 + half copies; blocks 1..32 pack W1 B-fragments.
__global__ void prep_kernel(const float* __restrict__ pivot,
                            const float* __restrict__ W1,
                            const float* __restrict__ b1,
                            const float* __restrict__ w2) {
    __shared__ float sp1[H_DIM];
    const int j = threadIdx.x;
    if (blockIdx.x == 0) {
        float s = b1[j];
#pragma unroll 8
        for (int d = 0; d < D_DIM; ++d)
            s = fmaf(pivot[d], W1[d * H_DIM + j], s);
        g_p1[j] = s;
        sp1[j] = s;
        __syncthreads();
        if (j < H_DIM / 2) {
            g_p1h2[j] = __floats2half2_rn(sp1[2 * j], sp1[2 * j + 1]);
            g_w2h2[j] = __floats2half2_rn(w2[2 * j], w2[2 * j + 1]);
        }
    } else {
        const int e = (blockIdx.x - 1) * 256 + j;
        const int tile = e >> 5;
        const int lane = e & 31;
        const int kt = tile / NT;
        const int nt = tile % NT;
        const int g = lane >> 2, t4 = lane & 3;
        const int k0 = kt * 16 + t4 * 2;
        const int col = nt * 8 + g;
        __half2 b0v = __floats2half2_rn(W1[(size_t)k0 * H_DIM + col],
                                        W1[(size_t)(k0 + 1) * H_DIM + col]);
        __half2 b1v = __floats2half2_rn(W1[(size_t)(k0 + 8) * H_DIM + col],
                                        W1[(size_t)(k0 + 9) * H_DIM + col]);
        g_Bfrag[tile * 32 + lane] = make_uint2(h2bits(b0v), h2bits(b1v));
    }
}

// ===================== Kernel 1: HMMA GEMM, u -> gmem =====================
__global__ __launch_bounds__(128)
void gemm_kernel(const float* __restrict__ r, int B) {
    __shared__ __half u_sh[BROWS][UPAD];

    const int lane = threadIdx.x & 31;
    const int wib  = threadIdx.x >> 5;
    const int row0 = (blockIdx.x * WARPS + wib) * WROWS;
    const int lrow0 = wib * WROWS;
    if (row0 < B) {
        // A fragments straight from gmem; quad covers full row -> norm inline
        const int g4 = lane >> 2, t4 = lane & 3;
        const float* pA = r + (size_t)(row0 + g4) * D_DIM;
        const float* pB = pA + (size_t)8 * D_DIM;

        unsigned a0[KT], a1[KT], a2[KT], a3[KT];
        float sl = 0.f, sh = 0.f;
#pragma unroll
        for (int kt = 0; kt < KT; ++kt) {
            const int base = kt * 16 + t4 * 2;
            float2 v0 = *(const float2*)(pA + base);
            float2 v1 = *(const float2*)(pB + base);
            float2 v2 = *(const float2*)(pA + base + 8);
            float2 v3 = *(const float2*)(pB + base + 8);
            sl = fmaf(v0.x, v0.x, fmaf(v0.y, v0.y, fmaf(v2.x, v2.x, fmaf(v2.y, v2.y, sl))));
            sh = fmaf(v1.x, v1.x, fmaf(v1.y, v1.y, fmaf(v3.x, v3.x, fmaf(v3.y, v3.y, sh))));
            a0[kt] = h2bits(__floats2half2_rn(v0.x, v0.y));
            a1[kt] = h2bits(__floats2half2_rn(v1.x, v1.y));
            a2[kt] = h2bits(__floats2half2_rn(v2.x, v2.y));
            a3[kt] = h2bits(__floats2half2_rn(v3.x, v3.y));
        }
        sl += __shfl_xor_sync(0xffffffffu, sl, 1);
        sl += __shfl_xor_sync(0xffffffffu, sl, 2);
        sh += __shfl_xor_sync(0xffffffffu, sh, 1);
        sh += __shfl_xor_sync(0xffffffffu, sh, 2);
        const __half2 il2 = __float2half2_rn(rsqrtf(sl));
        const __half2 ih2 = __float2half2_rn(rsqrtf(sh));
#pragma unroll
        for (int kt = 0; kt < KT; ++kt) {
            a0[kt] = hmul2b(a0[kt], il2);
            a2[kt] = hmul2b(a2[kt], il2);
            a1[kt] = hmul2b(a1[kt], ih2);
            a3[kt] = hmul2b(a3[kt], ih2);
        }

        // HMMA: 4 chunks of 64 cols
#pragma unroll
        for (int c = 0; c < 4; ++c) {
            float acc[8][4];
#pragma unroll
            for (int t = 0; t < 8; ++t)
#pragma unroll
                for (int q = 0; q < 4; ++q) acc[t][q] = 0.f;
#pragma unroll
            for (int kt = 0; kt < KT; ++kt) {
#pragma unroll
                for (int t = 0; t < 8; ++t) {
                    uint2 bf = g_Bfrag[(kt * NT + c * 8 + t) * 32 + lane];
                    mma16816(acc[t][0], acc[t][1], acc[t][2], acc[t][3],
                             a0[kt], a1[kt], a2[kt], a3[kt], bf.x, bf.y);
                }
            }
#pragma unroll
            for (int t = 0; t < 8; ++t) {
                const int col = (c * 8 + t) * 8 + t4 * 2;
                *(__half2*)&u_sh[lrow0 + g4][col]     = __floats2half2_rn(acc[t][0], acc[t][1]);
                *(__half2*)&u_sh[lrow0 + g4 + 8][col] = __floats2half2_rn(acc[t][2], acc[t][3]);
            }
        }
    }
    __syncthreads();

    // coalesced copy-out: 64 rows x 32 uint4
    const int base_row = blockIdx.x * BROWS;
    uint4* gu4 = (uint4*)g_u;
#pragma unroll
    for (int it = 0; it < 16; ++it) {
        const int li = it * 128 + threadIdx.x;      // 0..2047
        const int rw = li >> 5;                     // 0..63
        const int q  = li & 31;                     // 0..31
        if (base_row + rw < B)
            gu4[(size_t)(base_row + rw) * 32 + q] = *(const uint4*)&u_sh[rw][q * 8];
    }
}

// ===================== Kernel 2: 20-step recurrence =====================
__global__ __launch_bounds__(256)
void iter_kernel(const float* __restrict__ r,
                 const float* __restrict__ s_in,
                 const float* __restrict__ pivot,
                 const float* __restrict__ b2,
                 const int* __restrict__ n_iter_ptr,
                 float* __restrict__ out,
                 int B) {
    const int lane = threadIdx.x & 31;
    const int wib  = threadIdx.x >> 5;
    const int gB = lane >> 3, lB = lane & 7;
    const int row = blockIdx.x * 32 + wib * 4 + gB;
    if (row >= B) return;

    // r row: lane owns dims 16*lB .. 16*lB+15 (needed for norm + output)
    const float4* rv4 = (const float4*)(r + (size_t)row * D_DIM) + lB * 4;
    float4 rv[4];
    float ss = 0.f;
#pragma unroll
    for (int j = 0; j < 4; ++j) {
        rv[j] = rv4[j];
        ss = fmaf(rv[j].x, rv[j].x, fmaf(rv[j].y, rv[j].y,
             fmaf(rv[j].z, rv[j].z, fmaf(rv[j].w, rv[j].w, ss))));
    }
    ss += __shfl_xor_sync(0xffffffffu, ss, 1);
    ss += __shfl_xor_sync(0xffffffffu, ss, 2);
    ss += __shfl_xor_sync(0xffffffffu, ss, 4);
    const float inv_norm = rsqrtf(ss);

    // u slice: lane owns 32 halves (coalesced 4x uint4 per lane across group)
    __half2 u2[16];
    {
        const uint4* up = (const uint4*)(g_u + (size_t)row * H_DIM) + lB * 4;
#pragma unroll
        for (int v = 0; v < 4; ++v) {
            uint4 w = up[v];
            u2[v * 4 + 0] = *(__half2*)&w.x;
            u2[v * 4 + 1] = *(__half2*)&w.y;
            u2[v * 4 + 2] = *(__half2*)&w.z;
            u2[v * 4 + 3] = *(__half2*)&w.w;
        }
    }
    __half2 p12[16], w22[16];
    {
        const uint4* pp = (const uint4*)g_p1h2 + lB * 4;
        const uint4* wp = (const uint4*)g_w2h2 + lB * 4;
#pragma unroll
        for (int v = 0; v < 4; ++v) {
            uint4 a = pp[v], b = wp[v];
            p12[v * 4 + 0] = *(__half2*)&a.x; p12[v * 4 + 1] = *(__half2*)&a.y;
            p12[v * 4 + 2] = *(__half2*)&a.z; p12[v * 4 + 3] = *(__half2*)&a.w;
            w22[v * 4 + 0] = *(__half2*)&b.x; w22[v * 4 + 1] = *(__half2*)&b.y;
            w22[v * 4 + 2] = *(__half2*)&b.z; w22[v * 4 + 3] = *(__half2*)&b.w;
        }
    }

    const float b2v = b2[0];
    const int n = n_iter_ptr ? *n_iter_ptr : 20;
    const __half2 h2z = __floats2half2_rn(0.f, 0.f);

    float alpha = 0.f;
    for (int it = 0; it < n; ++it) {
        const __half2 a2h = __float2half2_rn(alpha);
        __half2 acc2a = h2z, acc2b = h2z;
#pragma unroll
        for (int q = 0; q < 16; q += 2) {
            __half2 za = __hfma2(a2h, u2[q],     p12[q]);
            __half2 zb = __hfma2(a2h, u2[q + 1], p12[q + 1]);
            acc2a = __hfma2(tanh2_fast(za), w22[q],     acc2a);
            acc2b = __hfma2(tanh2_fast(zb), w22[q + 1], acc2b);
        }
        __half2 acc2 = __hadd2(acc2a, acc2b);
        float accf = __low2float(acc2) + __high2float(acc2);
        accf += __shfl_xor_sync(0xffffffffu, accf, 1);
        accf += __shfl_xor_sync(0xffffffffu, accf, 2);
        accf += __shfl_xor_sync(0xffffffffu, accf, 4);
        alpha += 0.05f * (1.0f + tanh_fast(accf + b2v));
    }

    const float sv = s_in[row];
    const float sig = 1.0f / (1.0f + __expf(-sv));
    const float fscale = sig * alpha * inv_norm;

    const float4* pv4 = (const float4*)pivot + lB * 4;
    float4* ov4 = (float4*)(out + (size_t)row * D_DIM) + lB * 4;
#pragma unroll
    for (int jj = 0; jj < 4; ++jj) {
        float4 pv = pv4[jj];
        float4 o;
        o.x = fmaf(fscale, rv[jj].x, pv.x);
        o.y = fmaf(fscale, rv[jj].y, pv.y);
        o.z = fmaf(fscale, rv[jj].z, pv.z);
        o.w = fmaf(fscale, rv[jj].w, pv.w);
        ov4[jj] = o;
    }
}

extern "C" void kernel_launch(void* const* d_in, const int* in_sizes, int n_in,
                              void* d_out, int out_size) {
    const float* r     = (const float*)d_in[0];   // [B,128]
    const float* s     = (const float*)d_in[1];   // [B,1]
    const float* pivot = (const float*)d_in[2];   // [128]
    const float* W1    = (const float*)d_in[3];   // [128,256]
    const float* b1    = (const float*)d_in[4];   // [256]
    const float* w2    = (const float*)d_in[5];   // [256]
    const float* b2    = (const float*)d_in[6];   // [1]
    const int* n_iter  = (n_in > 7) ? (const int*)d_in[7] : nullptr;
    float* out = (float*)d_out;

    const int B = in_sizes[0] / D_DIM;

    prep_kernel<<<33, 256>>>(pivot, W1, b1, w2);

    const int gblocks = (B + BROWS - 1) / BROWS;
    gemm_kernel<<<gblocks, 128>>>(r, B);

    const int iblocks = (B + 31) / 32;
    iter_kernel<<<iblocks, 256>>>(r, s, pivot, b2, n_iter, out, B);
}